// round 2
// baseline (speedup 1.0000x reference)
#include <cuda_runtime.h>
#include <math.h>

#define B_SZ   2
#define T_SEQ  2048
#define C_EMB  1024
#define NHEAD  16
#define H_DIM  64
#define M_TOT  (B_SZ * T_SEQ)   // 4096

// Scratch (static device arrays: allocation-free per harness rules)
__device__ float g_qkv[(size_t)M_TOT * 3 * C_EMB];           // [B,T,3C]
__device__ float g_q[(size_t)B_SZ * NHEAD * T_SEQ * H_DIM];  // [B,H,T,D]
__device__ float g_k[(size_t)B_SZ * NHEAD * T_SEQ * H_DIM];
__device__ float g_v[(size_t)B_SZ * NHEAD * T_SEQ * H_DIM];
__device__ float g_y[(size_t)M_TOT * C_EMB];                 // [B,T,C]
__device__ float g_cos[T_SEQ * H_DIM];
__device__ float g_sin[T_SEQ * H_DIM];

// ---------------------------------------------------------------------------
// RoPE table: cos/sin in double precision (accurate for arguments up to ~2048)
// ---------------------------------------------------------------------------
__global__ void rope_table_kernel() {
    int i = blockIdx.x * blockDim.x + threadIdx.x;
    if (i >= T_SEQ * H_DIM) return;
    int t = i >> 6;
    int d = i & 63;
    double f = pow(10000.0, -(double)(d & 31) / 32.0);
    double ang = (double)t * f;
    g_cos[i] = (float)cos(ang);
    g_sin[i] = (float)sin(ang);
}

// ---------------------------------------------------------------------------
// SGEMM: C[M,N] = A[M,K] * B[N,K]^T   (both row-major; B is a weight matrix)
// 128x128 tile, BK=8, 256 threads, 8x8 micro-tile per thread.
// ---------------------------------------------------------------------------
__global__ __launch_bounds__(256)
void sgemm_nt_kernel(const float* __restrict__ A, const float* __restrict__ Bw,
                     float* __restrict__ Cm, int M, int N, int K) {
    __shared__ __align__(16) float As[8][132];
    __shared__ __align__(16) float Bs[8][132];

    int t  = threadIdx.x;
    int tx = t & 15;
    int ty = t >> 4;
    int bm = blockIdx.y;
    int bn = blockIdx.x;

    const float* Ablk = A  + (size_t)(bm * 128) * K;
    const float* Bblk = Bw + (size_t)(bn * 128) * K;

    int lr = t >> 1;         // 0..127 : row within tile
    int lk = (t & 1) * 4;    // 0 or 4 : k-offset

    float c[8][8];
#pragma unroll
    for (int i = 0; i < 8; i++)
#pragma unroll
        for (int j = 0; j < 8; j++) c[i][j] = 0.f;

    for (int k0 = 0; k0 < K; k0 += 8) {
        float4 av = *(const float4*)(Ablk + (size_t)lr * K + k0 + lk);
        float4 bv = *(const float4*)(Bblk + (size_t)lr * K + k0 + lk);
        __syncthreads();
        As[lk + 0][lr] = av.x; As[lk + 1][lr] = av.y;
        As[lk + 2][lr] = av.z; As[lk + 3][lr] = av.w;
        Bs[lk + 0][lr] = bv.x; Bs[lk + 1][lr] = bv.y;
        Bs[lk + 2][lr] = bv.z; Bs[lk + 3][lr] = bv.w;
        __syncthreads();
#pragma unroll
        for (int kk = 0; kk < 8; kk++) {
            float4 a0 = *(const float4*)&As[kk][ty * 4];
            float4 a1 = *(const float4*)&As[kk][64 + ty * 4];
            float4 b0 = *(const float4*)&Bs[kk][tx * 4];
            float4 b1 = *(const float4*)&Bs[kk][64 + tx * 4];
            float ar[8] = {a0.x, a0.y, a0.z, a0.w, a1.x, a1.y, a1.z, a1.w};
            float br[8] = {b0.x, b0.y, b0.z, b0.w, b1.x, b1.y, b1.z, b1.w};
#pragma unroll
            for (int i = 0; i < 8; i++)
#pragma unroll
                for (int j = 0; j < 8; j++) c[i][j] += ar[i] * br[j];
        }
    }

#pragma unroll
    for (int i = 0; i < 8; i++) {
        int mi = (i < 4) ? (ty * 4 + i) : (64 + ty * 4 + (i - 4));
        float* cp = Cm + (size_t)(bm * 128 + mi) * N + bn * 128;
        float4 v0 = make_float4(c[i][0], c[i][1], c[i][2], c[i][3]);
        float4 v1 = make_float4(c[i][4], c[i][5], c[i][6], c[i][7]);
        *(float4*)(cp + tx * 4)      = v0;
        *(float4*)(cp + 64 + tx * 4) = v1;
    }
}

// ---------------------------------------------------------------------------
// RoPE + split: g_qkv [B,T,3C] -> g_q/g_k (rotated), g_v, each [B,H,T,D]
// ---------------------------------------------------------------------------
__global__ void rope_split_kernel() {
    int i = blockIdx.x * blockDim.x + threadIdx.x;  // 0 .. B*T*H*D-1 (2^22)
    int d = i & 63;
    int h = (i >> 6) & 15;
    int t = (i >> 10) & 2047;
    int b = i >> 21;

    const float* base = g_qkv + (size_t)(b * T_SEQ + t) * (3 * C_EMB);
    float cs = g_cos[t * 64 + d];
    float sn = g_sin[t * 64 + d];

    int o  = h * 64 + d;
    int o2 = h * 64 + ((d < 32) ? (d + 32) : (d - 32));
    float sgn = (d < 32) ? -1.f : 1.f;

    float qv = base[o];
    float qp = base[o2];
    float kv = base[C_EMB + o];
    float kp = base[C_EMB + o2];

    size_t oi = ((size_t)(b * NHEAD + h) * T_SEQ + t) * H_DIM + d;
    g_q[oi] = qv * cs + sgn * qp * sn;
    g_k[oi] = kv * cs + sgn * kp * sn;
    g_v[oi] = base[2 * C_EMB + o];
}

// ---------------------------------------------------------------------------
// Flash attention (causal). blockIdx.x = q-tile (64 rows), blockIdx.y = b*H+h.
// 256 threads, 4x4 fragments over a 64x64 tile. Online softmax.
// Dynamic smem layout (floats):
//   QsT [64][64] (d-major)   4096
//   KsT [64][64] (d-major)   4096
//   Vs  [64][64] (n-major)   4096
//   Ss  [64][68]             4352
//   row_m[64] row_l[64] row_a[64]   192
//   pmax[256] psum[256]             512
// total 17344 floats = 69376 bytes
// ---------------------------------------------------------------------------
__global__ __launch_bounds__(256)
void attn_kernel(const float* __restrict__ Q, const float* __restrict__ Kg,
                 const float* __restrict__ Vg, float* __restrict__ Y) {
    extern __shared__ __align__(16) float sm[];
    float* QsT   = sm;
    float* KsT   = sm + 4096;
    float* Vs    = sm + 8192;
    float* Ss    = sm + 12288;
    float* row_m = sm + 12288 + 4352;
    float* row_l = row_m + 64;
    float* row_a = row_l + 64;
    float* pmax  = row_a + 64;
    float* psum  = pmax + 256;

    int t  = threadIdx.x;
    int tx = t & 15;
    int ty = t >> 4;
    int qt = blockIdx.x;
    int bh = blockIdx.y;

    const float* Qb = Q  + (size_t)bh * T_SEQ * H_DIM;
    const float* Kb = Kg + (size_t)bh * T_SEQ * H_DIM;
    const float* Vb = Vg + (size_t)bh * T_SEQ * H_DIM;

    // Load Q tile, transposed to [d][m]
    {
        int m  = t >> 2;
        int dg = (t & 3) * 16;
        const float* src = Qb + (size_t)(qt * 64 + m) * H_DIM + dg;
#pragma unroll
        for (int c4 = 0; c4 < 4; c4++) {
            float4 v = *(const float4*)(src + c4 * 4);
            int d = dg + c4 * 4;
            QsT[(d + 0) * 64 + m] = v.x;
            QsT[(d + 1) * 64 + m] = v.y;
            QsT[(d + 2) * 64 + m] = v.z;
            QsT[(d + 3) * 64 + m] = v.w;
        }
    }
    if (t < 64) { row_m[t] = -INFINITY; row_l[t] = 0.f; }

    float o[4][4];
#pragma unroll
    for (int i = 0; i < 4; i++)
#pragma unroll
        for (int j = 0; j < 4; j++) o[i][j] = 0.f;

    for (int kt = 0; kt <= qt; kt++) {
        __syncthreads();  // previous iteration done with Vs/KsT/Ss; Q visible
        // Load K (transposed) and V (natural)
        {
            int n  = t >> 2;
            int dg = (t & 3) * 16;
            const float* ks = Kb + (size_t)(kt * 64 + n) * H_DIM + dg;
            const float* vs = Vb + (size_t)(kt * 64 + n) * H_DIM + dg;
#pragma unroll
            for (int c4 = 0; c4 < 4; c4++) {
                float4 kv = *(const float4*)(ks + c4 * 4);
                int d = dg + c4 * 4;
                KsT[(d + 0) * 64 + n] = kv.x;
                KsT[(d + 1) * 64 + n] = kv.y;
                KsT[(d + 2) * 64 + n] = kv.z;
                KsT[(d + 3) * 64 + n] = kv.w;
                float4 vv = *(const float4*)(vs + c4 * 4);
                *(float4*)&Vs[n * 64 + d] = vv;
            }
        }
        __syncthreads();

        // S = (Q K^T) * scale
        float acc[4][4];
#pragma unroll
        for (int i = 0; i < 4; i++)
#pragma unroll
            for (int j = 0; j < 4; j++) acc[i][j] = 0.f;
#pragma unroll 8
        for (int k = 0; k < 64; k++) {
            float4 a = *(const float4*)&QsT[k * 64 + ty * 4];
            float4 b = *(const float4*)&KsT[k * 64 + tx * 4];
            float ar[4] = {a.x, a.y, a.z, a.w};
            float br[4] = {b.x, b.y, b.z, b.w};
#pragma unroll
            for (int i = 0; i < 4; i++)
#pragma unroll
                for (int j = 0; j < 4; j++) acc[i][j] += ar[i] * br[j];
        }
        bool diag = (kt == qt);
#pragma unroll
        for (int i = 0; i < 4; i++) {
            int m = ty * 4 + i;
#pragma unroll
            for (int j = 0; j < 4; j++) {
                int n = tx * 4 + j;
                float v = acc[i][j] * 0.125f;
                if (diag && n > m) v = -INFINITY;
                Ss[m * 68 + n] = v;
            }
        }
        __syncthreads();

        // Row max (4 partials per row)
        {
            int row = t >> 2, part = t & 3;
            const float* base = &Ss[row * 68 + part * 16];
            float mx = -INFINITY;
#pragma unroll
            for (int nn = 0; nn < 16; nn++) mx = fmaxf(mx, base[nn]);
            pmax[row * 4 + part] = mx;
        }
        __syncthreads();
        if (t < 64) {
            float mt = fmaxf(fmaxf(pmax[t * 4 + 0], pmax[t * 4 + 1]),
                             fmaxf(pmax[t * 4 + 2], pmax[t * 4 + 3]));
            float mo = row_m[t];
            float mn = fmaxf(mo, mt);
            row_m[t] = mn;
            row_a[t] = __expf(mo - mn);
        }
        __syncthreads();
        // Exponentiate + partial sums
        {
            int row = t >> 2, part = t & 3;
            float mn = row_m[row];
            float* base = &Ss[row * 68 + part * 16];
            float s = 0.f;
#pragma unroll
            for (int nn = 0; nn < 16; nn++) {
                float p = __expf(base[nn] - mn);
                base[nn] = p;
                s += p;
            }
            psum[row * 4 + part] = s;
        }
        __syncthreads();
        if (t < 64) {
            row_l[t] = row_l[t] * row_a[t] +
                       (psum[t * 4 + 0] + psum[t * 4 + 1] +
                        psum[t * 4 + 2] + psum[t * 4 + 3]);
        }

        // O = O*alpha + P @ V
        float am[4];
#pragma unroll
        for (int i = 0; i < 4; i++) am[i] = row_a[ty * 4 + i];
#pragma unroll
        for (int i = 0; i < 4; i++)
#pragma unroll
            for (int j = 0; j < 4; j++) o[i][j] *= am[i];
#pragma unroll 8
        for (int n = 0; n < 64; n++) {
            float4 bv = *(const float4*)&Vs[n * 64 + tx * 4];
            float p0 = Ss[(ty * 4 + 0) * 68 + n];
            float p1 = Ss[(ty * 4 + 1) * 68 + n];
            float p2 = Ss[(ty * 4 + 2) * 68 + n];
            float p3 = Ss[(ty * 4 + 3) * 68 + n];
            o[0][0] += p0 * bv.x; o[0][1] += p0 * bv.y; o[0][2] += p0 * bv.z; o[0][3] += p0 * bv.w;
            o[1][0] += p1 * bv.x; o[1][1] += p1 * bv.y; o[1][2] += p1 * bv.z; o[1][3] += p1 * bv.w;
            o[2][0] += p2 * bv.x; o[2][1] += p2 * bv.y; o[2][2] += p2 * bv.z; o[2][3] += p2 * bv.w;
            o[3][0] += p3 * bv.x; o[3][1] += p3 * bv.y; o[3][2] += p3 * bv.z; o[3][3] += p3 * bv.w;
        }
    }
    __syncthreads();

    // Finalize: divide by l, write to y [B,T,C] (heads interleaved)
    int b = bh >> 4;
    int h = bh & 15;
    size_t ybase = ((size_t)b * T_SEQ + (size_t)qt * 64) * C_EMB + h * 64;
#pragma unroll
    for (int i = 0; i < 4; i++) {
        int m = ty * 4 + i;
        float inv = 1.f / row_l[m];
        float4 v = make_float4(o[i][0] * inv, o[i][1] * inv,
                               o[i][2] * inv, o[i][3] * inv);
        *(float4*)&Y[ybase + (size_t)m * C_EMB + tx * 4] = v;
    }
}

// ---------------------------------------------------------------------------
extern "C" void kernel_launch(void* const* d_in, const int* in_sizes, int n_in,
                              void* d_out, int out_size) {
    const float* x      = (const float*)d_in[0];
    const float* w_qkv  = (const float*)d_in[1];
    const float* w_proj = (const float*)d_in[2];
    float* out = (float*)d_out;

    float *p_qkv, *p_q, *p_k, *p_v, *p_y;
    cudaGetSymbolAddress((void**)&p_qkv, g_qkv);
    cudaGetSymbolAddress((void**)&p_q, g_q);
    cudaGetSymbolAddress((void**)&p_k, g_k);
    cudaGetSymbolAddress((void**)&p_v, g_v);
    cudaGetSymbolAddress((void**)&p_y, g_y);

    // 1) RoPE tables
    rope_table_kernel<<<(T_SEQ * H_DIM + 255) / 256, 256>>>();

    // 2) QKV GEMM: [4096,1024] x [3072,1024]^T -> [4096,3072]
    sgemm_nt_kernel<<<dim3((3 * C_EMB) / 128, M_TOT / 128), 256>>>(
        x, w_qkv, p_qkv, M_TOT, 3 * C_EMB, C_EMB);

    // 3) RoPE + split into [B,H,T,D]
    rope_split_kernel<<<(B_SZ * T_SEQ * C_EMB) / 256, 256>>>();

    // 4) Flash attention
    int smem_bytes = 17344 * 4;
    cudaFuncSetAttribute(attn_kernel,
                         cudaFuncAttributeMaxDynamicSharedMemorySize, smem_bytes);
    attn_kernel<<<dim3(T_SEQ / 64, B_SZ * NHEAD), 256, smem_bytes>>>(
        p_q, p_k, p_v, p_y);

    // 5) Proj GEMM: [4096,1024] x [1024,1024]^T -> out [4096,1024]
    sgemm_nt_kernel<<<dim3(C_EMB / 128, M_TOT / 128), 256>>>(
        p_y, w_proj, out, M_TOT, C_EMB, C_EMB);
}

// round 3
// speedup vs baseline: 1.6673x; 1.6673x over previous
#include <cuda_runtime.h>
#include <math.h>
#include <stdint.h>

#define B_SZ   2
#define T_SEQ  2048
#define C_EMB  1024
#define NHEAD  16
#define H_DIM  64
#define M_TOT  (B_SZ * T_SEQ)   // 4096

// Scratch (static device arrays: allocation-free per harness rules)
__device__ float g_qkv[(size_t)M_TOT * 3 * C_EMB];           // [B,T,3C]
__device__ float g_q[(size_t)B_SZ * NHEAD * T_SEQ * H_DIM];  // [B,H,T,D]
__device__ float g_k[(size_t)B_SZ * NHEAD * T_SEQ * H_DIM];
__device__ float g_v[(size_t)B_SZ * NHEAD * T_SEQ * H_DIM];
__device__ float g_y[(size_t)M_TOT * C_EMB];                 // [B,T,C]
__device__ float g_cos[T_SEQ * H_DIM];
__device__ float g_sin[T_SEQ * H_DIM];

// ---------------------------------------------------------------------------
// helpers: tf32 convert + m16n8k8 tf32 mma
// ---------------------------------------------------------------------------
__device__ __forceinline__ uint32_t f2tf(float x) {
    uint32_t r;
    asm("cvt.rna.tf32.f32 %0, %1;" : "=r"(r) : "f"(x));
    return r;
}
__device__ __forceinline__ void mma_tf32(float* c,
                                         uint32_t a0, uint32_t a1, uint32_t a2, uint32_t a3,
                                         uint32_t b0, uint32_t b1) {
    asm volatile(
        "mma.sync.aligned.m16n8k8.row.col.f32.tf32.tf32.f32 "
        "{%0,%1,%2,%3}, {%4,%5,%6,%7}, {%8,%9}, {%0,%1,%2,%3};"
        : "+f"(c[0]), "+f"(c[1]), "+f"(c[2]), "+f"(c[3])
        : "r"(a0), "r"(a1), "r"(a2), "r"(a3), "r"(b0), "r"(b1));
}

// ---------------------------------------------------------------------------
// RoPE table: cos/sin in double precision
// ---------------------------------------------------------------------------
__global__ void rope_table_kernel() {
    int i = blockIdx.x * blockDim.x + threadIdx.x;
    if (i >= T_SEQ * H_DIM) return;
    int t = i >> 6;
    int d = i & 63;
    double f = pow(10000.0, -(double)(d & 31) / 32.0);
    double ang = (double)t * f;
    g_cos[i] = (float)cos(ang);
    g_sin[i] = (float)sin(ang);
}

// ---------------------------------------------------------------------------
// SGEMM via 3xTF32 mma: C[M,N] = A[M,K] * B[N,K]^T (both row-major)
// 128x128 tile, BK=16, 256 threads (8 warps), warp tile 32x64.
// hi/lo split on the fly -> ~fp32 accuracy.
// ---------------------------------------------------------------------------
#define ALD 20
__global__ __launch_bounds__(256)
void sgemm_tf32x3(const float* __restrict__ A, const float* __restrict__ Bw,
                  float* __restrict__ Cm, int M, int N, int K) {
    __shared__ __align__(16) float As[128 * ALD];
    __shared__ __align__(16) float Bs[128 * ALD];

    int t = threadIdx.x;
    int lane = t & 31, w = t >> 5;
    int gid = lane >> 2, tig = lane & 3;
    int mw = (w & 3) * 32;        // warp m-offset in tile
    int nw = (w >> 2) * 64;       // warp n-offset in tile
    int bm = blockIdx.y * 128, bn = blockIdx.x * 128;

    int lr = t >> 2;              // 0..63
    int lk = (t & 3) * 4;         // 0,4,8,12

    const float* Ag = A  + (size_t)(bm + lr) * K + lk;
    const float* Bg = Bw + (size_t)(bn + lr) * K + lk;

    float c[2][8][4] = {};

    for (int k0 = 0; k0 < K; k0 += 16) {
        float4 av0 = *(const float4*)(Ag);
        float4 av1 = *(const float4*)(Ag + (size_t)64 * K);
        float4 bv0 = *(const float4*)(Bg);
        float4 bv1 = *(const float4*)(Bg + (size_t)64 * K);
        Ag += 16; Bg += 16;

        __syncthreads();
        *(float4*)&As[lr * ALD + lk]        = av0;
        *(float4*)&As[(lr + 64) * ALD + lk] = av1;
        *(float4*)&Bs[lr * ALD + lk]        = bv0;
        *(float4*)&Bs[(lr + 64) * ALD + lk] = bv1;
        __syncthreads();

#pragma unroll
        for (int ks = 0; ks < 2; ks++) {
            int kb = ks * 8;
            uint32_t ah[2][4], al[2][4];
#pragma unroll
            for (int mt = 0; mt < 2; mt++) {
                int row = mw + mt * 16 + gid;
                float x0 = As[row * ALD + kb + tig];
                float x1 = As[(row + 8) * ALD + kb + tig];
                float x2 = As[row * ALD + kb + tig + 4];
                float x3 = As[(row + 8) * ALD + kb + tig + 4];
                ah[mt][0] = f2tf(x0); al[mt][0] = f2tf(x0 - __uint_as_float(ah[mt][0]));
                ah[mt][1] = f2tf(x1); al[mt][1] = f2tf(x1 - __uint_as_float(ah[mt][1]));
                ah[mt][2] = f2tf(x2); al[mt][2] = f2tf(x2 - __uint_as_float(ah[mt][2]));
                ah[mt][3] = f2tf(x3); al[mt][3] = f2tf(x3 - __uint_as_float(ah[mt][3]));
            }
            uint32_t bhf[8][2], blf[8][2];
#pragma unroll
            for (int nt = 0; nt < 8; nt++) {
                int n = nw + nt * 8 + gid;
                float y0 = Bs[n * ALD + kb + tig];
                float y1 = Bs[n * ALD + kb + tig + 4];
                bhf[nt][0] = f2tf(y0); blf[nt][0] = f2tf(y0 - __uint_as_float(bhf[nt][0]));
                bhf[nt][1] = f2tf(y1); blf[nt][1] = f2tf(y1 - __uint_as_float(bhf[nt][1]));
            }
#pragma unroll
            for (int mt = 0; mt < 2; mt++)
#pragma unroll
                for (int nt = 0; nt < 8; nt++) {
                    mma_tf32(c[mt][nt], ah[mt][0], ah[mt][1], ah[mt][2], ah[mt][3],
                             bhf[nt][0], bhf[nt][1]);
                    mma_tf32(c[mt][nt], ah[mt][0], ah[mt][1], ah[mt][2], ah[mt][3],
                             blf[nt][0], blf[nt][1]);
                    mma_tf32(c[mt][nt], al[mt][0], al[mt][1], al[mt][2], al[mt][3],
                             bhf[nt][0], bhf[nt][1]);
                }
        }
    }

#pragma unroll
    for (int mt = 0; mt < 2; mt++) {
        int row = bm + mw + mt * 16 + gid;
#pragma unroll
        for (int nt = 0; nt < 8; nt++) {
            int col = bn + nw + nt * 8 + 2 * tig;
            *(float2*)&Cm[(size_t)row * N + col] =
                make_float2(c[mt][nt][0], c[mt][nt][1]);
            *(float2*)&Cm[(size_t)(row + 8) * N + col] =
                make_float2(c[mt][nt][2], c[mt][nt][3]);
        }
    }
}

// ---------------------------------------------------------------------------
// RoPE + split: g_qkv [B,T,3C] -> g_q/g_k (rotated), g_v, each [B,H,T,D]
// ---------------------------------------------------------------------------
__global__ void rope_split_kernel() {
    int i = blockIdx.x * blockDim.x + threadIdx.x;
    int d = i & 63;
    int h = (i >> 6) & 15;
    int t = (i >> 10) & 2047;
    int b = i >> 21;

    const float* base = g_qkv + (size_t)(b * T_SEQ + t) * (3 * C_EMB);
    float cs = g_cos[t * 64 + d];
    float sn = g_sin[t * 64 + d];

    int o  = h * 64 + d;
    int o2 = h * 64 + ((d < 32) ? (d + 32) : (d - 32));
    float sgn = (d < 32) ? -1.f : 1.f;

    float qv = base[o];
    float qp = base[o2];
    float kv = base[C_EMB + o];
    float kp = base[C_EMB + o2];

    size_t oi = ((size_t)(b * NHEAD + h) * T_SEQ + t) * H_DIM + d;
    g_q[oi] = qv * cs + sgn * qp * sn;
    g_k[oi] = kv * cs + sgn * kp * sn;
    g_v[oi] = base[2 * C_EMB + o];
}

// ---------------------------------------------------------------------------
// Flash attention (causal) with tf32 mma.
// Block: 256 threads (8 warps), 128 Q rows per block (16 rows/warp),
// 64-key tiles. Q fragments register-resident; S and P*V via mma.
// Dynamic smem: Ksm[64*68] + Vsm[64*72] + Psm[128*68] floats.
// ---------------------------------------------------------------------------
#define KS_LD 68
#define VS_LD 72
#define PS_LD 68
#define SM_K_OFF 0
#define SM_V_OFF (64 * KS_LD)
#define SM_P_OFF (SM_V_OFF + 64 * VS_LD)
#define ATTN_SMEM_FLOATS (SM_P_OFF + 128 * PS_LD)

__global__ __launch_bounds__(256)
void attn_mma_kernel(const float* __restrict__ Q, const float* __restrict__ Kg,
                     const float* __restrict__ Vg, float* __restrict__ Y) {
    extern __shared__ __align__(16) float sm[];
    float* Ksm = sm + SM_K_OFF;
    float* Vsm = sm + SM_V_OFF;
    float* Psm = sm + SM_P_OFF;

    int t = threadIdx.x;
    int lane = t & 31, w = t >> 5;
    int gid = lane >> 2, tig = lane & 3;
    int qt = blockIdx.x;
    int bh = blockIdx.y;
    int wrow = w * 16;

    const float* Qb = Q  + (size_t)bh * T_SEQ * H_DIM;
    const float* Kb = Kg + (size_t)bh * T_SEQ * H_DIM;
    const float* Vb = Vg + (size_t)bh * T_SEQ * H_DIM;

    // Q fragments (persistent, pre-scaled by 1/8, tf32)
    int r0g = qt * 128 + wrow + gid;
    int r1g = r0g + 8;
    uint32_t qa[8][4];
    {
        const float* qp0 = Qb + (size_t)r0g * H_DIM;
        const float* qp1 = Qb + (size_t)r1g * H_DIM;
#pragma unroll
        for (int ks = 0; ks < 8; ks++) {
            int kk = ks * 8 + tig;
            qa[ks][0] = f2tf(qp0[kk] * 0.125f);
            qa[ks][1] = f2tf(qp1[kk] * 0.125f);
            qa[ks][2] = f2tf(qp0[kk + 4] * 0.125f);
            qa[ks][3] = f2tf(qp1[kk + 4] * 0.125f);
        }
    }

    float o[8][4] = {};
    float m0 = -INFINITY, m1 = -INFINITY;
    float l0 = 0.f, l1 = 0.f;

    float* pr0 = &Psm[(wrow + gid) * PS_LD];
    float* pr1 = &Psm[(wrow + gid + 8) * PS_LD];

    int ktmax = 2 * qt + 1;
    for (int kt = 0; kt <= ktmax; kt++) {
        __syncthreads();
        {   // load K,V tile (64 rows x 64 d)
            int row = t >> 2, dc = (t & 3) * 16;
            const float* kp = Kb + ((size_t)kt * 64 + row) * H_DIM + dc;
            const float* vp = Vb + ((size_t)kt * 64 + row) * H_DIM + dc;
#pragma unroll
            for (int j = 0; j < 4; j++) {
                *(float4*)&Ksm[row * KS_LD + dc + j * 4] = *(const float4*)(kp + j * 4);
                *(float4*)&Vsm[row * VS_LD + dc + j * 4] = *(const float4*)(vp + j * 4);
            }
        }
        __syncthreads();

        // S = Q * K^T (scaled)
        float s[8][4] = {};
#pragma unroll
        for (int ks = 0; ks < 8; ks++) {
            int kk = ks * 8 + tig;
#pragma unroll
            for (int nt = 0; nt < 8; nt++) {
                int n = nt * 8 + gid;
                uint32_t b0 = f2tf(Ksm[n * KS_LD + kk]);
                uint32_t b1 = f2tf(Ksm[n * KS_LD + kk + 4]);
                mma_tf32(s[nt], qa[ks][0], qa[ks][1], qa[ks][2], qa[ks][3], b0, b1);
            }
        }

        // causal mask (only tiles that can touch the diagonal)
        if (kt * 64 + 63 > qt * 128 + wrow) {
#pragma unroll
            for (int nt = 0; nt < 8; nt++) {
                int col = kt * 64 + nt * 8 + 2 * tig;
                if (col > r0g)     s[nt][0] = -INFINITY;
                if (col + 1 > r0g) s[nt][1] = -INFINITY;
                if (col > r1g)     s[nt][2] = -INFINITY;
                if (col + 1 > r1g) s[nt][3] = -INFINITY;
            }
        }

        // online softmax
        float mt0 = -INFINITY, mt1 = -INFINITY;
#pragma unroll
        for (int nt = 0; nt < 8; nt++) {
            mt0 = fmaxf(mt0, fmaxf(s[nt][0], s[nt][1]));
            mt1 = fmaxf(mt1, fmaxf(s[nt][2], s[nt][3]));
        }
        mt0 = fmaxf(mt0, __shfl_xor_sync(0xffffffffu, mt0, 1));
        mt0 = fmaxf(mt0, __shfl_xor_sync(0xffffffffu, mt0, 2));
        mt1 = fmaxf(mt1, __shfl_xor_sync(0xffffffffu, mt1, 1));
        mt1 = fmaxf(mt1, __shfl_xor_sync(0xffffffffu, mt1, 2));

        float mn0 = fmaxf(m0, mt0), mn1 = fmaxf(m1, mt1);
        float al0 = __expf(m0 - mn0), al1 = __expf(m1 - mn1);
        m0 = mn0; m1 = mn1;

        float ls0 = 0.f, ls1 = 0.f;
#pragma unroll
        for (int nt = 0; nt < 8; nt++) {
            s[nt][0] = __expf(s[nt][0] - mn0);
            s[nt][1] = __expf(s[nt][1] - mn0);
            s[nt][2] = __expf(s[nt][2] - mn1);
            s[nt][3] = __expf(s[nt][3] - mn1);
            ls0 += s[nt][0] + s[nt][1];
            ls1 += s[nt][2] + s[nt][3];
        }
        ls0 += __shfl_xor_sync(0xffffffffu, ls0, 1);
        ls0 += __shfl_xor_sync(0xffffffffu, ls0, 2);
        ls1 += __shfl_xor_sync(0xffffffffu, ls1, 1);
        ls1 += __shfl_xor_sync(0xffffffffu, ls1, 2);
        l0 = l0 * al0 + ls0;
        l1 = l1 * al1 + ls1;

#pragma unroll
        for (int nt = 0; nt < 8; nt++) {
            o[nt][0] *= al0; o[nt][1] *= al0;
            o[nt][2] *= al1; o[nt][3] *= al1;
        }

        // stage P (warp-private rows)
#pragma unroll
        for (int nt = 0; nt < 8; nt++) {
            *(float2*)&pr0[nt * 8 + 2 * tig] = make_float2(s[nt][0], s[nt][1]);
            *(float2*)&pr1[nt * 8 + 2 * tig] = make_float2(s[nt][2], s[nt][3]);
        }
        __syncwarp();

        // O += P * V
#pragma unroll
        for (int ks = 0; ks < 8; ks++) {
            int kk = ks * 8;
            uint32_t pa0 = f2tf(pr0[kk + tig]);
            uint32_t pa1 = f2tf(pr1[kk + tig]);
            uint32_t pa2 = f2tf(pr0[kk + tig + 4]);
            uint32_t pa3 = f2tf(pr1[kk + tig + 4]);
#pragma unroll
            for (int nt = 0; nt < 8; nt++) {
                int d = nt * 8 + gid;
                uint32_t b0 = f2tf(Vsm[(kk + tig) * VS_LD + d]);
                uint32_t b1 = f2tf(Vsm[(kk + tig + 4) * VS_LD + d]);
                mma_tf32(o[nt], pa0, pa1, pa2, pa3, b0, b1);
            }
        }
        __syncwarp();
    }

    // finalize + write to y [B,T,C], heads interleaved
    float inv0 = 1.f / l0, inv1 = 1.f / l1;
    int b = bh >> 4, h = bh & 15;
    float* y0 = Y + ((size_t)b * T_SEQ + r0g) * C_EMB + h * 64;
    float* y1 = Y + ((size_t)b * T_SEQ + r1g) * C_EMB + h * 64;
#pragma unroll
    for (int nt = 0; nt < 8; nt++) {
        int col = nt * 8 + 2 * tig;
        *(float2*)&y0[col] = make_float2(o[nt][0] * inv0, o[nt][1] * inv0);
        *(float2*)&y1[col] = make_float2(o[nt][2] * inv1, o[nt][3] * inv1);
    }
}

// ---------------------------------------------------------------------------
extern "C" void kernel_launch(void* const* d_in, const int* in_sizes, int n_in,
                              void* d_out, int out_size) {
    const float* x      = (const float*)d_in[0];
    const float* w_qkv  = (const float*)d_in[1];
    const float* w_proj = (const float*)d_in[2];
    float* out = (float*)d_out;

    float *p_qkv, *p_q, *p_k, *p_v, *p_y;
    cudaGetSymbolAddress((void**)&p_qkv, g_qkv);
    cudaGetSymbolAddress((void**)&p_q, g_q);
    cudaGetSymbolAddress((void**)&p_k, g_k);
    cudaGetSymbolAddress((void**)&p_v, g_v);
    cudaGetSymbolAddress((void**)&p_y, g_y);

    // 1) RoPE tables
    rope_table_kernel<<<(T_SEQ * H_DIM + 255) / 256, 256>>>();

    // 2) QKV GEMM: [4096,1024] x [3072,1024]^T -> [4096,3072]
    sgemm_tf32x3<<<dim3((3 * C_EMB) / 128, M_TOT / 128), 256>>>(
        x, w_qkv, p_qkv, M_TOT, 3 * C_EMB, C_EMB);

    // 3) RoPE + split into [B,H,T,D]
    rope_split_kernel<<<(B_SZ * T_SEQ * C_EMB) / 256, 256>>>();

    // 4) Flash attention (tf32 mma)
    int smem_bytes = ATTN_SMEM_FLOATS * 4;
    cudaFuncSetAttribute(attn_mma_kernel,
                         cudaFuncAttributeMaxDynamicSharedMemorySize, smem_bytes);
    attn_mma_kernel<<<dim3(T_SEQ / 128, B_SZ * NHEAD), 256, smem_bytes>>>(
        p_q, p_k, p_v, p_y);

    // 5) Proj GEMM: [4096,1024] x [1024,1024]^T -> out [4096,1024]
    sgemm_tf32x3<<<dim3(C_EMB / 128, M_TOT / 128), 256>>>(
        p_y, w_proj, out, M_TOT, C_EMB, C_EMB);
}